// round 5
// baseline (speedup 1.0000x reference)
#include <cuda_runtime.h>
#include <cstdint>

#define MAXN 10000
#define MAXE 160000
#define HEADS 2
#define NEG_SLOPE 0.2f

// ---------------- scratch (device globals; no allocation) ----------------
__device__ float g_h  [MAXN * 128];     // MLP hidden
__device__ float g_x1 [MAXN * 512];     // MLP out
__device__ float g_y  [MAXN * 512];     // x1 @ Wg
__device__ float g_x2 [MAXN * 512];     // GCN out (relu)
__device__ float g_xh [MAXN * 1024];    // x2 @ Wa
__device__ float g_dinv[MAXN];
__device__ float g_as [MAXN * HEADS];
__device__ float g_ad [MAXN * HEADS];
__device__ float g_m  [MAXN * HEADS];
__device__ float g_den[MAXN * HEADS];
__device__ float g_ebuf[MAXE * HEADS];  // edge logit, then exp(e-m)
// flat int32 edge arrays (dtype-robust)
__device__ int  g_is64;
__device__ int  g_srcA[MAXE];
__device__ int  g_dstA[MAXE];
// CSR by destination
__device__ int  g_cnt[MAXN];
__device__ int  g_off[MAXN];
__device__ int  g_cur[MAXN];
__device__ int2 g_csr[MAXE];            // (src, edge_id)

// ---------------- helpers ----------------
__device__ __forceinline__ float leaky(float v) {
    return v >= 0.f ? v : NEG_SLOPE * v;
}

__device__ __forceinline__ void atomicMaxFloat(float* addr, float val) {
    if (val >= 0.f)
        atomicMax((int*)addr, __float_as_int(val));
    else
        atomicMin((unsigned int*)addr, __float_as_uint(val));
}

// ---------------- edge dtype detect + convert ----------------
// If buffer is int64 (values < 2^31, little-endian), every odd int32 word is 0.
// If buffer is int32 node-ids, odd words are random ids (all-zero prob ~ 0).
__global__ void edge_detect_kernel(const int* __restrict__ raw, int E) {
    if (threadIdx.x == 0 && blockIdx.x == 0) {
        int n = (E < 256) ? E : 256;
        int all0 = 1;
        for (int i = 0; i < n; i++)
            if (raw[2 * i + 1] != 0) { all0 = 0; break; }
        g_is64 = all0;
    }
}

__global__ void edge_convert_kernel(const int* __restrict__ raw, int E) {
    int e = blockIdx.x * blockDim.x + threadIdx.x;
    if (e >= E) return;
    if (g_is64) {
        g_srcA[e] = raw[2 * (size_t)e];
        g_dstA[e] = raw[2 * ((size_t)E + e)];
    } else {
        g_srcA[e] = raw[e];
        g_dstA[e] = raw[(size_t)E + e];
    }
}

// ---------------- tiled SGEMM: C[M,N] = act(A[M,K] @ B[K,N] + bias) ----------------
// 128x128 block tile, TK=16, 256 threads, 8x8 microtile, double-buffered smem.
// Requires K % 16 == 0, N % 128 == 0 (true for all four GEMMs). M guarded.
__global__ __launch_bounds__(256) void sgemm128_kernel(
    const float* __restrict__ A, const float* __restrict__ B,
    const float* __restrict__ bias, float* __restrict__ C,
    int M, int K, int N, int relu)
{
    __shared__ float As[2][16][132];   // [buf][k][m], padded
    __shared__ float Bs[2][16][132];   // [buf][k][n], padded
    const int tid = threadIdx.x;
    const int tx  = tid & 15;          // n dim
    const int ty  = tid >> 4;          // m dim
    const int row0 = blockIdx.y * 128;
    const int col0 = blockIdx.x * 128;

    const int am0 = (tid      ) >> 2, ak0 = (tid      ) & 3;
    const int am1 = (tid + 256) >> 2, ak1 = (tid + 256) & 3;
    const int bk0 = (tid      ) >> 5, bn0 = (tid      ) & 31;
    const int bk1 = (tid + 256) >> 5, bn1 = (tid + 256) & 31;

    float acc[8][8] = {};
    float4 pa0, pa1, pb0, pb1;

    {
        int gm0 = row0 + am0, gm1 = row0 + am1;
        pa0 = (gm0 < M) ? *(const float4*)(A + (size_t)gm0 * K + ak0 * 4) : make_float4(0.f,0.f,0.f,0.f);
        pa1 = (gm1 < M) ? *(const float4*)(A + (size_t)gm1 * K + ak1 * 4) : make_float4(0.f,0.f,0.f,0.f);
        pb0 = *(const float4*)(B + (size_t)bk0 * N + col0 + bn0 * 4);
        pb1 = *(const float4*)(B + (size_t)bk1 * N + col0 + bn1 * 4);
    }
    As[0][ak0*4+0][am0] = pa0.x; As[0][ak0*4+1][am0] = pa0.y;
    As[0][ak0*4+2][am0] = pa0.z; As[0][ak0*4+3][am0] = pa0.w;
    As[0][ak1*4+0][am1] = pa1.x; As[0][ak1*4+1][am1] = pa1.y;
    As[0][ak1*4+2][am1] = pa1.z; As[0][ak1*4+3][am1] = pa1.w;
    *(float4*)&Bs[0][bk0][bn0*4] = pb0;
    *(float4*)&Bs[0][bk1][bn1*4] = pb1;
    __syncthreads();

    int buf = 0;
    for (int k0 = 16; k0 < K; k0 += 16) {
        {
            int gm0 = row0 + am0, gm1 = row0 + am1;
            pa0 = (gm0 < M) ? *(const float4*)(A + (size_t)gm0 * K + k0 + ak0 * 4) : make_float4(0.f,0.f,0.f,0.f);
            pa1 = (gm1 < M) ? *(const float4*)(A + (size_t)gm1 * K + k0 + ak1 * 4) : make_float4(0.f,0.f,0.f,0.f);
            pb0 = *(const float4*)(B + (size_t)(k0 + bk0) * N + col0 + bn0 * 4);
            pb1 = *(const float4*)(B + (size_t)(k0 + bk1) * N + col0 + bn1 * 4);
        }
        #pragma unroll
        for (int kk = 0; kk < 16; kk++) {
            float a[8], b[8];
            #pragma unroll
            for (int i = 0; i < 4; i++) {
                ((float2*)a)[i] = ((float2*)&As[buf][kk][ty * 8])[i];
                ((float2*)b)[i] = ((float2*)&Bs[buf][kk][tx * 8])[i];
            }
            #pragma unroll
            for (int i = 0; i < 8; i++)
                #pragma unroll
                for (int j = 0; j < 8; j++)
                    acc[i][j] = fmaf(a[i], b[j], acc[i][j]);
        }
        int nb = buf ^ 1;
        As[nb][ak0*4+0][am0] = pa0.x; As[nb][ak0*4+1][am0] = pa0.y;
        As[nb][ak0*4+2][am0] = pa0.z; As[nb][ak0*4+3][am0] = pa0.w;
        As[nb][ak1*4+0][am1] = pa1.x; As[nb][ak1*4+1][am1] = pa1.y;
        As[nb][ak1*4+2][am1] = pa1.z; As[nb][ak1*4+3][am1] = pa1.w;
        *(float4*)&Bs[nb][bk0][bn0*4] = pb0;
        *(float4*)&Bs[nb][bk1][bn1*4] = pb1;
        __syncthreads();
        buf = nb;
    }
    #pragma unroll
    for (int kk = 0; kk < 16; kk++) {
        float a[8], b[8];
        #pragma unroll
        for (int i = 0; i < 4; i++) {
            ((float2*)a)[i] = ((float2*)&As[buf][kk][ty * 8])[i];
            ((float2*)b)[i] = ((float2*)&Bs[buf][kk][tx * 8])[i];
        }
        #pragma unroll
        for (int i = 0; i < 8; i++)
            #pragma unroll
            for (int j = 0; j < 8; j++)
                acc[i][j] = fmaf(a[i], b[j], acc[i][j]);
    }

    #pragma unroll
    for (int i = 0; i < 8; i++) {
        int gm = row0 + ty * 8 + i;
        if (gm < M) {
            #pragma unroll
            for (int j = 0; j < 8; j++) {
                int gn = col0 + tx * 8 + j;
                float v = acc[i][j];
                if (bias) v += bias[gn];
                if (relu) v = fmaxf(v, 0.f);
                C[(size_t)gm * N + gn] = v;
            }
        }
    }
}

// ---------------- CSR build (bucket edges by destination) ----------------
__global__ void csr_zero_kernel(int Nn) {
    int i = blockIdx.x * blockDim.x + threadIdx.x;
    if (i < Nn) g_cnt[i] = 0;
}

__global__ void csr_count_kernel(int E) {
    int e = blockIdx.x * blockDim.x + threadIdx.x;
    if (e < E) atomicAdd(&g_cnt[g_dstA[e]], 1);
}

// single-block exclusive scan of g_cnt -> g_off (and g_cur); also dinv = rsqrt(cnt+1)
__global__ __launch_bounds__(1024) void csr_scan_kernel(int Nn) {
    __shared__ int part[1024];
    const int tid = threadIdx.x;
    const int per = (Nn + 1023) / 1024;     // <= 16
    const int base = tid * per;
    int local[16];
    int sum = 0;
    for (int i = 0; i < per; i++) {
        int v = (base + i < Nn) ? g_cnt[base + i] : 0;
        local[i] = sum;
        sum += v;
    }
    part[tid] = sum;
    __syncthreads();
    for (int off = 1; off < 1024; off <<= 1) {
        int v = (tid >= off) ? part[tid - off] : 0;
        __syncthreads();
        part[tid] += v;
        __syncthreads();
    }
    int excl = (tid == 0) ? 0 : part[tid - 1];
    for (int i = 0; i < per; i++) {
        int idx = base + i;
        if (idx < Nn) {
            int o = excl + local[i];
            g_off[idx] = o;
            g_cur[idx] = o;
            g_dinv[idx] = rsqrtf((float)g_cnt[idx] + 1.0f);  // +1 self loop
        }
    }
}

__global__ void csr_fill_kernel(int E) {
    int e = blockIdx.x * blockDim.x + threadIdx.x;
    if (e < E) {
        int d = g_dstA[e];
        int pos = atomicAdd(&g_cur[d], 1);
        g_csr[pos] = make_int2(g_srcA[e], e);
    }
}

// ---------------- GCN gather: x2[d] = relu( sum_in norm*y[s] + dinv^2*y[d] + bg ) ----------------
__global__ __launch_bounds__(128) void gcn_gather_kernel(const float* __restrict__ bg) {
    const int d = blockIdx.x;
    const int lane = threadIdx.x;           // 0..127, 4 floats each
    const float dd = g_dinv[d];

    float4 acc = ((const float4*)(g_y + (size_t)d * 512))[lane];
    float sc = dd * dd;
    acc.x *= sc; acc.y *= sc; acc.z *= sc; acc.w *= sc;

    const int beg = g_off[d];
    const int num = g_cnt[d];
    __shared__ int ssrc[128];

    for (int c0 = 0; c0 < num; c0 += 128) {
        int n = min(128, num - c0);
        if (lane < n) ssrc[lane] = g_csr[beg + c0 + lane].x;
        __syncthreads();
        #pragma unroll 4
        for (int j = 0; j < n; j++) {
            int s = ssrc[j];
            float norm = g_dinv[s] * dd;
            float4 v = ((const float4*)(g_y + (size_t)s * 512))[lane];
            acc.x = fmaf(v.x, norm, acc.x);
            acc.y = fmaf(v.y, norm, acc.y);
            acc.z = fmaf(v.z, norm, acc.z);
            acc.w = fmaf(v.w, norm, acc.w);
        }
        __syncthreads();
    }

    float4 b = ((const float4*)bg)[lane];
    acc.x = fmaxf(acc.x + b.x, 0.f);
    acc.y = fmaxf(acc.y + b.y, 0.f);
    acc.z = fmaxf(acc.z + b.z, 0.f);
    acc.w = fmaxf(acc.w + b.w, 0.f);
    ((float4*)(g_x2 + (size_t)d * 512))[lane] = acc;
}

// ---------------- GAT ----------------
// a_s / a_d dots: one warp per (node, head); also seeds m with self-loop logit
__global__ void att_dot_kernel(const float* __restrict__ att_src,
                               const float* __restrict__ att_dst, int Nn)
{
    int gw   = (blockIdx.x * blockDim.x + threadIdx.x) >> 5;
    int lane = threadIdx.x & 31;
    if (gw >= Nn * HEADS) return;
    int n = gw >> 1, h = gw & 1;
    const float* xr = g_xh + (size_t)n * 1024 + h * 512;
    float ss = 0.f, sd = 0.f;
    #pragma unroll 4
    for (int c = lane; c < 512; c += 32) {
        float v = xr[c];
        ss += v * att_src[h * 512 + c];
        sd += v * att_dst[h * 512 + c];
    }
    #pragma unroll
    for (int o = 16; o; o >>= 1) {
        ss += __shfl_xor_sync(0xffffffffu, ss, o);
        sd += __shfl_xor_sync(0xffffffffu, sd, o);
    }
    if (lane == 0) {
        g_as[n * 2 + h] = ss;
        g_ad[n * 2 + h] = sd;
        g_m [n * 2 + h] = leaky(ss + sd);   // self-loop logit seeds segment max
    }
}

// per-edge logit + running max over dst
__global__ void gat_edge_max_kernel(int E) {
    int idx = blockIdx.x * blockDim.x + threadIdx.x;
    if (idx >= E * HEADS) return;
    int e = idx >> 1, h = idx & 1;
    int s = g_srcA[e];
    int d = g_dstA[e];
    float lg = leaky(g_as[s * 2 + h] + g_ad[d * 2 + h]);
    g_ebuf[idx] = lg;
    atomicMaxFloat(&g_m[d * 2 + h], lg);
}

// denom seed = exp(self_logit - m)
__global__ void gat_den_init_kernel(int Nn) {
    int i = blockIdx.x * blockDim.x + threadIdx.x;
    if (i < Nn * HEADS) g_den[i] = expf(leaky(g_as[i] + g_ad[i]) - g_m[i]);
}

// ex = exp(e - m[d]); accumulate denom
__global__ void gat_edge_exp_kernel(int E) {
    int idx = blockIdx.x * blockDim.x + threadIdx.x;
    if (idx >= E * HEADS) return;
    int e = idx >> 1, h = idx & 1;
    int d = g_dstA[e];
    float ex = expf(g_ebuf[idx] - g_m[d * 2 + h]);
    g_ebuf[idx] = ex;
    atomicAdd(&g_den[d * 2 + h], ex);
}

// out[d] = sum_in alpha*xh[s] + alpha_self*xh[d] + ba   (gather, no atomics)
__global__ __launch_bounds__(256) void gat_gather_kernel(
    float* __restrict__ out, const float* __restrict__ ba)
{
    const int d = blockIdx.x;
    const int lane = threadIdx.x;           // 0..255, 4 floats each -> 1024
    const int h = lane >> 7;                // head for these 4 channels
    const int ih = d * 2 + h;

    const float idn = 1.0f / g_den[ih];
    const float alpha_self = expf(leaky(g_as[ih] + g_ad[ih]) - g_m[ih]) * idn;

    float4 acc = ((const float4*)(g_xh + (size_t)d * 1024))[lane];
    acc.x *= alpha_self; acc.y *= alpha_self; acc.z *= alpha_self; acc.w *= alpha_self;

    const int beg = g_off[d];
    const int num = g_cnt[d];
    __shared__ int2 sbuf[256];

    for (int c0 = 0; c0 < num; c0 += 256) {
        int n = min(256, num - c0);
        if (lane < n) sbuf[lane] = g_csr[beg + c0 + lane];
        __syncthreads();
        #pragma unroll 4
        for (int j = 0; j < n; j++) {
            int s   = sbuf[j].x;
            int eid = sbuf[j].y;
            float alpha = g_ebuf[eid * 2 + h] * idn;
            float4 v = ((const float4*)(g_xh + (size_t)s * 1024))[lane];
            acc.x = fmaf(v.x, alpha, acc.x);
            acc.y = fmaf(v.y, alpha, acc.y);
            acc.z = fmaf(v.z, alpha, acc.z);
            acc.w = fmaf(v.w, alpha, acc.w);
        }
        __syncthreads();
    }

    float4 b = ((const float4*)ba)[lane];
    acc.x += b.x; acc.y += b.y; acc.z += b.z; acc.w += b.w;
    ((float4*)(out + (size_t)d * 1024))[lane] = acc;
}

// ---------------- launch ----------------
extern "C" void kernel_launch(void* const* d_in, const int* in_sizes, int n_in,
                              void* d_out, int out_size)
{
    const float* z    = (const float*)d_in[0];
    const int*   eraw = (const int*)d_in[1];    // int32 OR int64 (detected on device)
    const float* W1   = (const float*)d_in[2];
    const float* b1   = (const float*)d_in[3];
    const float* W2   = (const float*)d_in[4];
    const float* b2   = (const float*)d_in[5];
    const float* Wg   = (const float*)d_in[6];
    const float* bg   = (const float*)d_in[7];
    const float* Wa   = (const float*)d_in[8];
    const float* asrc = (const float*)d_in[9];
    const float* adst = (const float*)d_in[10];
    const float* ba   = (const float*)d_in[11];
    float*       out  = (float*)d_out;

    const int Nn = in_sizes[0] / 64;     // 10000
    const int E  = in_sizes[1] / 2;      // 160000 (element count is dtype-invariant)

    float *ph, *px1, *py, *px2, *pxh;
    cudaGetSymbolAddress((void**)&ph,  g_h);
    cudaGetSymbolAddress((void**)&px1, g_x1);
    cudaGetSymbolAddress((void**)&py,  g_y);
    cudaGetSymbolAddress((void**)&px2, g_x2);
    cudaGetSymbolAddress((void**)&pxh, g_xh);

    int mb = (Nn + 127) / 128;

    // edge index normalize + CSR build (independent of features)
    edge_detect_kernel<<<1, 32>>>(eraw, E);
    edge_convert_kernel<<<(E + 255) / 256, 256>>>(eraw, E);
    csr_zero_kernel<<<(Nn + 255) / 256, 256>>>(Nn);
    csr_count_kernel<<<(E + 255) / 256, 256>>>(E);
    csr_scan_kernel<<<1, 1024>>>(Nn);
    csr_fill_kernel<<<(E + 255) / 256, 256>>>(E);

    // MLP
    sgemm128_kernel<<<dim3(1, mb), 256>>>(z,   W1, b1, ph,  Nn, 64,  128, 1);
    sgemm128_kernel<<<dim3(4, mb), 256>>>(ph,  W2, b2, px1, Nn, 128, 512, 1);

    // GCN
    sgemm128_kernel<<<dim3(4, mb), 256>>>(px1, Wg, nullptr, py, Nn, 512, 512, 0);
    gcn_gather_kernel<<<Nn, 128>>>(bg);

    // GAT
    sgemm128_kernel<<<dim3(8, mb), 256>>>(px2, Wa, nullptr, pxh, Nn, 512, 1024, 0);
    att_dot_kernel<<<(Nn * HEADS * 32 + 255) / 256, 256>>>(asrc, adst, Nn);
    gat_edge_max_kernel<<<(E * HEADS + 255) / 256, 256>>>(E);
    gat_den_init_kernel<<<(Nn * HEADS + 255) / 256, 256>>>(Nn);
    gat_edge_exp_kernel<<<(E * HEADS + 255) / 256, 256>>>(E);
    gat_gather_kernel<<<Nn, 256>>>(out, ba);
}

// round 11
// speedup vs baseline: 1.4480x; 1.4480x over previous
#include <cuda_runtime.h>
#include <cuda_bf16.h>
#include <mma.h>
#include <cstdint>

using namespace nvcuda;

#define MAXN 10000
#define MPAD 10112            // 79 * 128
#define MAXE 160000
#define HEADS 2
#define NEG_SLOPE 0.2f

// ---------------- scratch (device globals; no allocation) ----------------
__device__ float g_C  [MPAD * 1024];    // shared fp32 GEMM output scratch
__device__ float g_dinv[MAXN];
__device__ float g_as [MAXN * HEADS];
__device__ float g_ad [MAXN * HEADS];
__device__ float g_m  [MAXN * HEADS];
__device__ float g_den[MAXN * HEADS];
__device__ float g_ebuf[MAXE * HEADS];
// bf16 split operand buffers (padded to MPAD rows; ping-pong A, shared B)
__device__ __nv_bfloat16 g_A1h[MPAD * 512], g_A1l[MPAD * 512];
__device__ __nv_bfloat16 g_A2h[MPAD * 512], g_A2l[MPAD * 512];
__device__ __nv_bfloat16 g_Bh [1024 * 512], g_Bl [1024 * 512];
// edge arrays + CSR
__device__ int  g_is64;
__device__ int  g_srcA[MAXE];
__device__ int  g_dstA[MAXE];
__device__ int  g_cnt[MAXN];
__device__ int  g_off[MAXN];
__device__ int  g_cur[MAXN];
__device__ int2 g_csr[MAXE];

// ---------------- helpers ----------------
__device__ __forceinline__ float leaky(float v) {
    return v >= 0.f ? v : NEG_SLOPE * v;
}

__device__ __forceinline__ void atomicMaxFloat(float* addr, float val) {
    if (val >= 0.f)
        atomicMax((int*)addr, __float_as_int(val));
    else
        atomicMin((unsigned int*)addr, __float_as_uint(val));
}

__device__ __forceinline__ void split2(float v, __nv_bfloat16& h, __nv_bfloat16& l) {
    h = __float2bfloat16(v);
    l = __float2bfloat16(v - __bfloat162float(h));
}

// ---------------- fp32 -> bf16 hi/lo split kernels ----------------
__global__ void conv_split_kernel(const float* __restrict__ src,
                                  __nv_bfloat16* __restrict__ h,
                                  __nv_bfloat16* __restrict__ l, int n) {
    int i = blockIdx.x * blockDim.x + threadIdx.x;
    if (i < n) {
        __nv_bfloat16 hi, lo;
        split2(src[i], hi, lo);
        h[i] = hi; l[i] = lo;
    }
}

// W [K,N] fp32 -> Wt hi/lo [N,K] bf16
__global__ void wt_split_kernel(const float* __restrict__ W,
                                __nv_bfloat16* __restrict__ th,
                                __nv_bfloat16* __restrict__ tl, int K, int N) {
    int i = blockIdx.x * blockDim.x + threadIdx.x;
    if (i < N * K) {
        int n = i / K, k = i - n * K;
        __nv_bfloat16 hi, lo;
        split2(W[(size_t)k * N + n], hi, lo);
        th[i] = hi; tl[i] = lo;
    }
}

// epilogue: v = relu(C + bias) then split -> h/l
__global__ void epi_split_kernel(const float* __restrict__ C,
                                 const float* __restrict__ bias,
                                 __nv_bfloat16* __restrict__ h,
                                 __nv_bfloat16* __restrict__ l,
                                 int total, int N) {
    int i = blockIdx.x * blockDim.x + threadIdx.x;
    if (i < total) {
        float v = fmaxf(C[i] + bias[i % N], 0.f);
        __nv_bfloat16 hi, lo;
        split2(v, hi, lo);
        h[i] = hi; l[i] = lo;
    }
}

// ---------------- WMMA bf16-split GEMM ----------------
// C[M,N] = A @ Bt^T ; A=[MPAD,K] hi/lo bf16 row-major, Bt=[N,K] hi/lo row-major.
// Block tile 128x128, BK=32, 8 warps (2x4 16x16 frags per warp = 32x64 warp tile).
// 3 split terms: AhBh + AhBl + AlBh, fp32 accumulate. No bounds checks (padded).
__global__ __launch_bounds__(256) void gemm_wmma_kernel(
    const __nv_bfloat16* __restrict__ Ah, const __nv_bfloat16* __restrict__ Al,
    const __nv_bfloat16* __restrict__ Bh, const __nv_bfloat16* __restrict__ Bl,
    float* __restrict__ C, int K, int N)
{
    __shared__ __nv_bfloat16 sAh[128][40], sAl[128][40];
    __shared__ __nv_bfloat16 sBh[128][40], sBl[128][40];

    const int tid = threadIdx.x;
    const int wid = tid >> 5;
    const int wm = wid & 3;        // warp row 0..3  -> 32 rows each
    const int wn = wid >> 2;       // warp col 0..1  -> 64 cols each
    const int row0 = blockIdx.y * 128;
    const int col0 = blockIdx.x * 128;

    wmma::fragment<wmma::accumulator, 16, 16, 16, float> acc[2][4];
    #pragma unroll
    for (int mi = 0; mi < 2; mi++)
        #pragma unroll
        for (int ni = 0; ni < 4; ni++)
            wmma::fill_fragment(acc[mi][ni], 0.f);

    for (int k0 = 0; k0 < K; k0 += 32) {
        // stage tiles: 512 uint4 slots per matrix, 2 per thread
        #pragma unroll
        for (int i = 0; i < 2; i++) {
            int s = tid + i * 256;       // 0..511
            int r = s >> 2;              // 0..127
            int c = s & 3;               // x8 bf16
            const uint4* pah = (const uint4*)(Ah + (size_t)(row0 + r) * K + k0);
            const uint4* pal = (const uint4*)(Al + (size_t)(row0 + r) * K + k0);
            const uint4* pbh = (const uint4*)(Bh + (size_t)(col0 + r) * K + k0);
            const uint4* pbl = (const uint4*)(Bl + (size_t)(col0 + r) * K + k0);
            *(uint4*)&sAh[r][c * 8] = pah[c];
            *(uint4*)&sAl[r][c * 8] = pal[c];
            *(uint4*)&sBh[r][c * 8] = pbh[c];
            *(uint4*)&sBl[r][c * 8] = pbl[c];
        }
        __syncthreads();

        #pragma unroll
        for (int ks = 0; ks < 2; ks++) {
            wmma::fragment<wmma::matrix_a, 16, 16, 16, __nv_bfloat16, wmma::row_major> fah[2], fal[2];
            wmma::fragment<wmma::matrix_b, 16, 16, 16, __nv_bfloat16, wmma::col_major> fbh[4], fbl[4];
            #pragma unroll
            for (int mi = 0; mi < 2; mi++) {
                wmma::load_matrix_sync(fah[mi], &sAh[wm * 32 + mi * 16][ks * 16], 40);
                wmma::load_matrix_sync(fal[mi], &sAl[wm * 32 + mi * 16][ks * 16], 40);
            }
            #pragma unroll
            for (int ni = 0; ni < 4; ni++) {
                wmma::load_matrix_sync(fbh[ni], &sBh[wn * 64 + ni * 16][ks * 16], 40);
                wmma::load_matrix_sync(fbl[ni], &sBl[wn * 64 + ni * 16][ks * 16], 40);
            }
            #pragma unroll
            for (int mi = 0; mi < 2; mi++)
                #pragma unroll
                for (int ni = 0; ni < 4; ni++) {
                    wmma::mma_sync(acc[mi][ni], fah[mi], fbh[ni], acc[mi][ni]);
                    wmma::mma_sync(acc[mi][ni], fah[mi], fbl[ni], acc[mi][ni]);
                    wmma::mma_sync(acc[mi][ni], fal[mi], fbh[ni], acc[mi][ni]);
                }
        }
        __syncthreads();
    }

    #pragma unroll
    for (int mi = 0; mi < 2; mi++)
        #pragma unroll
        for (int ni = 0; ni < 4; ni++)
            wmma::store_matrix_sync(
                C + (size_t)(row0 + wm * 32 + mi * 16) * N + col0 + wn * 64 + ni * 16,
                acc[mi][ni], N, wmma::mem_row_major);
}

// ---------------- edge dtype detect + convert ----------------
__global__ void edge_detect_kernel(const int* __restrict__ raw, int E) {
    if (threadIdx.x == 0 && blockIdx.x == 0) {
        int n = (E < 256) ? E : 256;
        int all0 = 1;
        for (int i = 0; i < n; i++)
            if (raw[2 * i + 1] != 0) { all0 = 0; break; }
        g_is64 = all0;
    }
}

__global__ void edge_convert_kernel(const int* __restrict__ raw, int E) {
    int e = blockIdx.x * blockDim.x + threadIdx.x;
    if (e >= E) return;
    if (g_is64) {
        g_srcA[e] = raw[2 * (size_t)e];
        g_dstA[e] = raw[2 * ((size_t)E + e)];
    } else {
        g_srcA[e] = raw[e];
        g_dstA[e] = raw[(size_t)E + e];
    }
}

// ---------------- CSR build ----------------
__global__ void csr_zero_kernel(int Nn) {
    int i = blockIdx.x * blockDim.x + threadIdx.x;
    if (i < Nn) g_cnt[i] = 0;
}

__global__ void csr_count_kernel(int E) {
    int e = blockIdx.x * blockDim.x + threadIdx.x;
    if (e < E) atomicAdd(&g_cnt[g_dstA[e]], 1);
}

__global__ __launch_bounds__(1024) void csr_scan_kernel(int Nn) {
    __shared__ int part[1024];
    const int tid = threadIdx.x;
    const int per = (Nn + 1023) / 1024;
    const int base = tid * per;
    int local[16];
    int sum = 0;
    for (int i = 0; i < per; i++) {
        int v = (base + i < Nn) ? g_cnt[base + i] : 0;
        local[i] = sum;
        sum += v;
    }
    part[tid] = sum;
    __syncthreads();
    for (int off = 1; off < 1024; off <<= 1) {
        int v = (tid >= off) ? part[tid - off] : 0;
        __syncthreads();
        part[tid] += v;
        __syncthreads();
    }
    int excl = (tid == 0) ? 0 : part[tid - 1];
    for (int i = 0; i < per; i++) {
        int idx = base + i;
        if (idx < Nn) {
            int o = excl + local[i];
            g_off[idx] = o;
            g_cur[idx] = o;
            g_dinv[idx] = rsqrtf((float)g_cnt[idx] + 1.0f);
        }
    }
}

__global__ void csr_fill_kernel(int E) {
    int e = blockIdx.x * blockDim.x + threadIdx.x;
    if (e < E) {
        int d = g_dstA[e];
        int pos = atomicAdd(&g_cur[d], 1);
        g_csr[pos] = make_int2(g_srcA[e], e);
    }
}

// ---------------- GCN gather (reads g_C stride 512) -> relu -> split into A2 ----------------
__global__ __launch_bounds__(128) void gcn_gather_kernel(const float* __restrict__ bg) {
    const int d = blockIdx.x;
    const int lane = threadIdx.x;
    const float dd = g_dinv[d];

    float4 acc = ((const float4*)(g_C + (size_t)d * 512))[lane];
    float sc = dd * dd;
    acc.x *= sc; acc.y *= sc; acc.z *= sc; acc.w *= sc;

    const int beg = g_off[d];
    const int num = g_cnt[d];
    __shared__ int ssrc[128];

    for (int c0 = 0; c0 < num; c0 += 128) {
        int n = min(128, num - c0);
        if (lane < n) ssrc[lane] = g_csr[beg + c0 + lane].x;
        __syncthreads();
        #pragma unroll 4
        for (int j = 0; j < n; j++) {
            int s = ssrc[j];
            float norm = g_dinv[s] * dd;
            float4 v = ((const float4*)(g_C + (size_t)s * 512))[lane];
            acc.x = fmaf(v.x, norm, acc.x);
            acc.y = fmaf(v.y, norm, acc.y);
            acc.z = fmaf(v.z, norm, acc.z);
            acc.w = fmaf(v.w, norm, acc.w);
        }
        __syncthreads();
    }

    float4 b = ((const float4*)bg)[lane];
    float o[4] = { fmaxf(acc.x + b.x, 0.f), fmaxf(acc.y + b.y, 0.f),
                   fmaxf(acc.z + b.z, 0.f), fmaxf(acc.w + b.w, 0.f) };
    size_t base = (size_t)d * 512 + lane * 4;
    #pragma unroll
    for (int t = 0; t < 4; t++) {
        __nv_bfloat16 hi, lo;
        split2(o[t], hi, lo);
        g_A2h[base + t] = hi;
        g_A2l[base + t] = lo;
    }
}

// ---------------- GAT (features in g_C, stride 1024) ----------------
__global__ void att_dot_kernel(const float* __restrict__ att_src,
                               const float* __restrict__ att_dst, int Nn)
{
    int gw   = (blockIdx.x * blockDim.x + threadIdx.x) >> 5;
    int lane = threadIdx.x & 31;
    if (gw >= Nn * HEADS) return;
    int n = gw >> 1, h = gw & 1;
    const float* xr = g_C + (size_t)n * 1024 + h * 512;
    float ss = 0.f, sd = 0.f;
    #pragma unroll 4
    for (int c = lane; c < 512; c += 32) {
        float v = xr[c];
        ss += v * att_src[h * 512 + c];
        sd += v * att_dst[h * 512 + c];
    }
    #pragma unroll
    for (int o = 16; o; o >>= 1) {
        ss += __shfl_xor_sync(0xffffffffu, ss, o);
        sd += __shfl_xor_sync(0xffffffffu, sd, o);
    }
    if (lane == 0) {
        g_as[n * 2 + h] = ss;
        g_ad[n * 2 + h] = sd;
        g_m [n * 2 + h] = leaky(ss + sd);
    }
}

__global__ void gat_edge_max_kernel(int E) {
    int idx = blockIdx.x * blockDim.x + threadIdx.x;
    if (idx >= E * HEADS) return;
    int e = idx >> 1, h = idx & 1;
    int s = g_srcA[e];
    int d = g_dstA[e];
    float lg = leaky(g_as[s * 2 + h] + g_ad[d * 2 + h]);
    g_ebuf[idx] = lg;
    atomicMaxFloat(&g_m[d * 2 + h], lg);
}

__global__ void gat_den_init_kernel(int Nn) {
    int i = blockIdx.x * blockDim.x + threadIdx.x;
    if (i < Nn * HEADS) g_den[i] = expf(leaky(g_as[i] + g_ad[i]) - g_m[i]);
}

__global__ void gat_edge_exp_kernel(int E) {
    int idx = blockIdx.x * blockDim.x + threadIdx.x;
    if (idx >= E * HEADS) return;
    int e = idx >> 1, h = idx & 1;
    int d = g_dstA[e];
    float ex = expf(g_ebuf[idx] - g_m[d * 2 + h]);
    g_ebuf[idx] = ex;
    atomicAdd(&g_den[d * 2 + h], ex);
}

__global__ __launch_bounds__(256) void gat_gather_kernel(
    float* __restrict__ out, const float* __restrict__ ba)
{
    const int d = blockIdx.x;
    const int lane = threadIdx.x;
    const int h = lane >> 7;
    const int ih = d * 2 + h;

    const float idn = 1.0f / g_den[ih];
    const float alpha_self = expf(leaky(g_as[ih] + g_ad[ih]) - g_m[ih]) * idn;

    float4 acc = ((const float4*)(g_C + (size_t)d * 1024))[lane];
    acc.x *= alpha_self; acc.y *= alpha_self; acc.z *= alpha_self; acc.w *= alpha_self;

    const int beg = g_off[d];
    const int num = g_cnt[d];
    __shared__ int2 sbuf[256];

    for (int c0 = 0; c0 < num; c0 += 256) {
        int n = min(256, num - c0);
        if (lane < n) sbuf[lane] = g_csr[beg + c0 + lane];
        __syncthreads();
        #pragma unroll 4
        for (int j = 0; j < n; j++) {
            int s   = sbuf[j].x;
            int eid = sbuf[j].y;
            float alpha = g_ebuf[eid * 2 + h] * idn;
            float4 v = ((const float4*)(g_C + (size_t)s * 1024))[lane];
            acc.x = fmaf(v.x, alpha, acc.x);
            acc.y = fmaf(v.y, alpha, acc.y);
            acc.z = fmaf(v.z, alpha, acc.z);
            acc.w = fmaf(v.w, alpha, acc.w);
        }
        __syncthreads();
    }

    float4 b = ((const float4*)ba)[lane];
    acc.x += b.x; acc.y += b.y; acc.z += b.z; acc.w += b.w;
    ((float4*)(out + (size_t)d * 1024))[lane] = acc;
}

// ---------------- launch ----------------
extern "C" void kernel_launch(void* const* d_in, const int* in_sizes, int n_in,
                              void* d_out, int out_size)
{
    const float* z    = (const float*)d_in[0];
    const int*   eraw = (const int*)d_in[1];
    const float* W1   = (const float*)d_in[2];
    const float* b1   = (const float*)d_in[3];
    const float* W2   = (const float*)d_in[4];
    const float* b2   = (const float*)d_in[5];
    const float* Wg   = (const float*)d_in[6];
    const float* bg   = (const float*)d_in[7];
    const float* Wa   = (const float*)d_in[8];
    const float* asrc = (const float*)d_in[9];
    const float* adst = (const float*)d_in[10];
    const float* ba   = (const float*)d_in[11];
    float*       out  = (float*)d_out;

    const int Nn = in_sizes[0] / 64;     // 10000
    const int E  = in_sizes[1] / 2;      // 160000

    float* pc;
    cudaGetSymbolAddress((void**)&pc, g_C);
    __nv_bfloat16 *a1h, *a1l, *a2h, *a2l, *bh, *bl;
    cudaGetSymbolAddress((void**)&a1h, g_A1h);
    cudaGetSymbolAddress((void**)&a1l, g_A1l);
    cudaGetSymbolAddress((void**)&a2h, g_A2h);
    cudaGetSymbolAddress((void**)&a2l, g_A2l);
    cudaGetSymbolAddress((void**)&bh,  g_Bh);
    cudaGetSymbolAddress((void**)&bl,  g_Bl);

    const int mb = MPAD / 128;           // 79 tiles cover all padded rows

    // input split (feeds GEMM1), then edge pipeline
    conv_split_kernel<<<(Nn * 64 + 255) / 256, 256>>>(z, a1h, a1l, Nn * 64);
    edge_detect_kernel<<<1, 32>>>(eraw, E);
    edge_convert_kernel<<<(E + 255) / 256, 256>>>(eraw, E);
    csr_zero_kernel<<<(Nn + 255) / 256, 256>>>(Nn);
    csr_count_kernel<<<(E + 255) / 256, 256>>>(E);
    csr_scan_kernel<<<1, 1024>>>(Nn);
    csr_fill_kernel<<<(E + 255) / 256, 256>>>(E);

    // GEMM1: z @ W1 -> g_C (stride 128); epi: relu+b1 -> split A2
    wt_split_kernel<<<(128 * 64 + 255) / 256, 256>>>(W1, bh, bl, 64, 128);
    gemm_wmma_kernel<<<dim3(1, mb), 256>>>(a1h, a1l, bh, bl, pc, 64, 128);
    epi_split_kernel<<<(Nn * 128 + 255) / 256, 256>>>(pc, b1, a2h, a2l, Nn * 128, 128);

    // GEMM2: h @ W2 -> g_C (stride 512); epi: relu+b2 -> split A1
    wt_split_kernel<<<(512 * 128 + 255) / 256, 256>>>(W2, bh, bl, 128, 512);
    gemm_wmma_kernel<<<dim3(4, mb), 256>>>(a2h, a2l, bh, bl, pc, 128, 512);
    epi_split_kernel<<<(Nn * 512 + 255) / 256, 256>>>(pc, b2, a1h, a1l, Nn * 512, 512);

    // GEMM3: x1 @ Wg -> g_C fp32 (stride 512); GCN gather reads g_C
    wt_split_kernel<<<(512 * 512 + 255) / 256, 256>>>(Wg, bh, bl, 512, 512);
    gemm_wmma_kernel<<<dim3(4, mb), 256>>>(a1h, a1l, bh, bl, pc, 512, 512);
    gcn_gather_kernel<<<Nn, 128>>>(bg);

    // GEMM4: x2 @ Wa -> g_C fp32 (stride 1024); GAT reads g_C
    wt_split_kernel<<<(1024 * 512 + 255) / 256, 256>>>(Wa, bh, bl, 512, 1024);
    gemm_wmma_kernel<<<dim3(8, mb), 256>>>(a2h, a2l, bh, bl, pc, 512, 1024);

    // GAT
    att_dot_kernel<<<(Nn * HEADS * 32 + 255) / 256, 256>>>(asrc, adst, Nn);
    gat_edge_max_kernel<<<(E * HEADS + 255) / 256, 256>>>(E);
    gat_den_init_kernel<<<(Nn * HEADS + 255) / 256, 256>>>(Nn);
    gat_edge_exp_kernel<<<(E * HEADS + 255) / 256, 256>>>(E);
    gat_gather_kernel<<<Nn, 256>>>(out, ba);
}